// round 1
// baseline (speedup 1.0000x reference)
#include <cuda_runtime.h>

#define BB 32
#define SS 512
#define DD 1024

#define TS 128   // s-tile
#define TI 128   // i-tile
#define TK 32    // k-chunk

// scratch (module-load allocated, allowed)
__device__ float g_inv_e[BB * SS];        // 64 KB
__device__ float g_a2[BB * 2 * DD];       // 256 KB, normalized aspect duplicated

// ---------------- Kernel A: per-row inverse norms of embeddings ----------------
__global__ void enorm_kernel(const float* __restrict__ e) {
    int b = blockIdx.y, s = blockIdx.x;
    int t = threadIdx.x;                   // 256 threads
    const float4* r4 = (const float4*)(e + ((size_t)b * SS + s) * DD);
    float4 v = r4[t];                      // DD/4 == 256 exactly
    float sum = v.x * v.x + v.y * v.y + v.z * v.z + v.w * v.w;
    #pragma unroll
    for (int o = 16; o; o >>= 1) sum += __shfl_xor_sync(0xffffffffu, sum, o);
    __shared__ float ws[8];
    if ((t & 31) == 0) ws[t >> 5] = sum;
    __syncthreads();
    if (t == 0) {
        float tot = 0.f;
        #pragma unroll
        for (int i = 0; i < 8; i++) tot += ws[i];
        g_inv_e[b * SS + s] = (tot > 0.f) ? rsqrtf(tot) : 0.f;
    }
}

// ---------------- Kernel B: normalize aspect, write duplicated a2 ----------------
__global__ void anorm_kernel(const float* __restrict__ a) {
    int b = blockIdx.x;
    int t = threadIdx.x;                   // 256 threads
    const float4* r4 = (const float4*)(a + (size_t)b * DD);
    float4 v = r4[t];
    float sum = v.x * v.x + v.y * v.y + v.z * v.z + v.w * v.w;
    #pragma unroll
    for (int o = 16; o; o >>= 1) sum += __shfl_xor_sync(0xffffffffu, sum, o);
    __shared__ float ws[8];
    __shared__ float s_inv;
    if ((t & 31) == 0) ws[t >> 5] = sum;
    __syncthreads();
    if (t == 0) {
        float tot = 0.f;
        #pragma unroll
        for (int i = 0; i < 8; i++) tot += ws[i];
        s_inv = (tot > 0.f) ? rsqrtf(tot) : 0.f;
    }
    __syncthreads();
    float inv = s_inv;
    float4 o4 = make_float4(v.x * inv, v.y * inv, v.z * inv, v.w * inv);
    float* dst = g_a2 + (size_t)b * 2 * DD;
    ((float4*)dst)[t] = o4;
    ((float4*)(dst + DD))[t] = o4;
}

// ---------------- Kernel C: circulant GEMM ----------------
// out[b, s, i] = sum_d e_n[b,s,d] * a2[b, DD + d - i]
// block tile: 128 (s) x 128 (i), 256 threads, 8x8 per-thread register tile.
__global__ void __launch_bounds__(256, 2)
circgemm_kernel(const float* __restrict__ e, float* __restrict__ out) {
    __shared__ float Es[TS][TK + 1];       // [s][k], padded: 128*33*4 = 16.9 KB
    __shared__ float As[2 * DD];           // 8 KB

    const int b      = blockIdx.z;
    const int s_base = blockIdx.y * TS;
    const int i_base = blockIdx.x * TI;

    const int t  = threadIdx.x;
    const int tx = t & 15;                 // i-group
    const int ty = t >> 4;                 // s-group

    // load normalized duplicated aspect into smem (once)
    {
        const float4* src = (const float4*)(g_a2 + (size_t)b * 2 * DD);
        float4* dst = (float4*)As;
        #pragma unroll
        for (int j = 0; j < 2; j++) dst[t + 256 * j] = src[t + 256 * j];
    }

    float acc[8][8];
    #pragma unroll
    for (int h = 0; h < 8; h++)
        #pragma unroll
        for (int g = 0; g < 8; g++) acc[h][g] = 0.f;

    const int rowg = t >> 3;               // 0..31
    const int colg = (t & 7) * 4;          // 0,4,...,28

    for (int k0 = 0; k0 < DD; k0 += TK) {
        // load E tile (128 rows x 32 k) with row-norm applied
        #pragma unroll
        for (int p = 0; p < 4; p++) {
            int s = rowg + p * 32;
            float inv = g_inv_e[b * SS + s_base + s];
            float4 v = *(const float4*)(e + ((size_t)b * SS + s_base + s) * DD + k0 + colg);
            Es[s][colg + 0] = v.x * inv;
            Es[s][colg + 1] = v.y * inv;
            Es[s][colg + 2] = v.z * inv;
            Es[s][colg + 3] = v.w * inv;
        }
        __syncthreads();

        #pragma unroll 8
        for (int k = 0; k < TK; k++) {
            const int abase = DD + k0 + k - i_base - tx;
            float av[8], ev[8];
            #pragma unroll
            for (int g = 0; g < 8; g++) av[g] = As[abase - 16 * g];
            #pragma unroll
            for (int h = 0; h < 8; h++) ev[h] = Es[ty + 16 * h][k];
            #pragma unroll
            for (int h = 0; h < 8; h++)
                #pragma unroll
                for (int g = 0; g < 8; g++)
                    acc[h][g] = fmaf(ev[h], av[g], acc[h][g]);
        }
        __syncthreads();
    }

    // write 8x8 tile
    #pragma unroll
    for (int h = 0; h < 8; h++) {
        float* orow = out + ((size_t)b * SS + s_base + ty + 16 * h) * DD + i_base + tx;
        #pragma unroll
        for (int g = 0; g < 8; g++) orow[16 * g] = acc[h][g];
    }
}

extern "C" void kernel_launch(void* const* d_in, const int* in_sizes, int n_in,
                              void* d_out, int out_size) {
    const float* emb = (const float*)d_in[0];   // (32, 512, 1024) f32
    const float* asp = (const float*)d_in[1];   // (32, 1024) f32
    float* out = (float*)d_out;                 // (32, 512, 1024) f32

    enorm_kernel<<<dim3(SS, BB), 256>>>(emb);
    anorm_kernel<<<BB, 256>>>(asp);
    circgemm_kernel<<<dim3(DD / TI, SS / TS, BB), 256>>>(emb, out);
}

// round 3
// speedup vs baseline: 1.3871x; 1.3871x over previous
#include <cuda_runtime.h>
#include <cuda_bf16.h>
#include <cstdint>

#define BB 32
#define SS 512
#define DD 1024

// ---- device scratch (module-load allocated; no runtime allocs) ----
__device__ __nv_bfloat16 g_eh[BB * SS * DD];          // 32 MB  normalized E hi
__device__ __nv_bfloat16 g_el[BB * SS * DD];          // 32 MB  normalized E lo
__device__ __nv_bfloat16 g_ah2[BB * 2 * DD];          // 128 KB aspect hi, duplicated
__device__ __nv_bfloat16 g_al2[BB * 2 * DD];          // 128 KB aspect lo, duplicated
__device__ __nv_bfloat16 g_ch[(size_t)BB * DD * DD];  // 64 MB circulant hi
__device__ __nv_bfloat16 g_cl[(size_t)BB * DD * DD];  // 64 MB circulant lo

// ============================ helpers ============================
__device__ __forceinline__ uint32_t smem_u32(const void* p) {
    uint32_t a;
    asm("{ .reg .u64 t; cvta.to.shared.u64 t, %1; cvt.u32.u64 %0, t; }" : "=r"(a) : "l"(p));
    return a;
}
__device__ __forceinline__ void cpasync16(uint32_t dst, const void* src) {
    asm volatile("cp.async.cg.shared.global [%0], [%1], 16;" :: "r"(dst), "l"(src));
}
__device__ __forceinline__ void ldsm4(uint32_t* r, uint32_t a) {
    asm volatile("ldmatrix.sync.aligned.m8n8.x4.shared.b16 {%0,%1,%2,%3}, [%4];"
                 : "=r"(r[0]), "=r"(r[1]), "=r"(r[2]), "=r"(r[3]) : "r"(a));
}
__device__ __forceinline__ void mma16816(float* c, const uint32_t* a, const uint32_t* b) {
    asm volatile(
        "mma.sync.aligned.m16n8k16.row.col.f32.bf16.bf16.f32 "
        "{%0,%1,%2,%3}, {%4,%5,%6,%7}, {%8,%9}, {%0,%1,%2,%3};"
        : "+f"(c[0]), "+f"(c[1]), "+f"(c[2]), "+f"(c[3])
        : "r"(a[0]), "r"(a[1]), "r"(a[2]), "r"(a[3]), "r"(b[0]), "r"(b[1]));
}

// ============================ prep kernels ============================
__global__ void anorm_kernel(const float* __restrict__ a) {
    int b = blockIdx.x, t = threadIdx.x;  // 256 threads
    float4 v = ((const float4*)(a + (size_t)b * DD))[t];
    float sum = v.x * v.x + v.y * v.y + v.z * v.z + v.w * v.w;
    #pragma unroll
    for (int o = 16; o; o >>= 1) sum += __shfl_xor_sync(0xffffffffu, sum, o);
    __shared__ float ws[8];
    __shared__ float s_inv;
    if ((t & 31) == 0) ws[t >> 5] = sum;
    __syncthreads();
    if (t == 0) {
        float tot = 0.f;
        #pragma unroll
        for (int i = 0; i < 8; i++) tot += ws[i];
        s_inv = (tot > 0.f) ? rsqrtf(tot) : 0.f;
    }
    __syncthreads();
    float inv = s_inv;
    float n[4] = {v.x * inv, v.y * inv, v.z * inv, v.w * inv};
    #pragma unroll
    for (int j = 0; j < 4; j++) {
        __nv_bfloat16 h = __float2bfloat16(n[j]);
        __nv_bfloat16 l = __float2bfloat16(n[j] - __bfloat162float(h));
        size_t base = (size_t)b * 2 * DD + 4 * t + j;
        g_ah2[base] = h;  g_ah2[base + DD] = h;
        g_al2[base] = l;  g_al2[base + DD] = l;
    }
}

__global__ void esplit_kernel(const float* __restrict__ e) {
    int b = blockIdx.y, s = blockIdx.x, t = threadIdx.x;  // 256 threads
    size_t row = (size_t)b * SS + s;
    float4 v = ((const float4*)(e + row * DD))[t];
    float sum = v.x * v.x + v.y * v.y + v.z * v.z + v.w * v.w;
    #pragma unroll
    for (int o = 16; o; o >>= 1) sum += __shfl_xor_sync(0xffffffffu, sum, o);
    __shared__ float ws[8];
    __shared__ float s_inv;
    if ((t & 31) == 0) ws[t >> 5] = sum;
    __syncthreads();
    if (t == 0) {
        float tot = 0.f;
        #pragma unroll
        for (int i = 0; i < 8; i++) tot += ws[i];
        s_inv = (tot > 0.f) ? rsqrtf(tot) : 0.f;
    }
    __syncthreads();
    float inv = s_inv;
    float n[4] = {v.x * inv, v.y * inv, v.z * inv, v.w * inv};
    ushort4 ph, pl;
    unsigned short* hp = &ph.x;
    unsigned short* lp = &pl.x;
    #pragma unroll
    for (int j = 0; j < 4; j++) {
        __nv_bfloat16 h = __float2bfloat16(n[j]);
        __nv_bfloat16 l = __float2bfloat16(n[j] - __bfloat162float(h));
        hp[j] = __bfloat16_as_ushort(h);
        lp[j] = __bfloat16_as_ushort(l);
    }
    ((ushort4*)(g_eh + row * DD))[t] = ph;
    ((ushort4*)(g_el + row * DD))[t] = pl;
}

// circulant rows: c[b][n][k] = a2[b][DD + k - n]
__global__ void circ_kernel() {
    int n = blockIdx.x, b = blockIdx.y, t = threadIdx.x;   // 256 threads
    size_t src = (size_t)b * 2 * DD + DD - n + 4 * t;
    ushort4 ph, pl;
    unsigned short* hp = &ph.x;
    unsigned short* lp = &pl.x;
    #pragma unroll
    for (int j = 0; j < 4; j++) {
        hp[j] = __bfloat16_as_ushort(g_ah2[src + j]);
        lp[j] = __bfloat16_as_ushort(g_al2[src + j]);
    }
    size_t dst = ((size_t)b * DD + n) * DD + 4 * t;
    *((ushort4*)(g_ch + dst)) = ph;
    *((ushort4*)(g_cl + dst)) = pl;
}

// ============================ GEMM kernel ============================
// out[b, s_base+m, i_base+n] = sum_k E[m][k] * C[n][k]   (3-way bf16 split)
// CTA 128x128, 8 warps (warp tile 64x32), K-chunk 32, double-buffered cp.async.
#define ROWB 80                 // smem row stride: 5 x 16B -> conflict-free ldmatrix
#define TILE_B (128 * ROWB)     // 10240 bytes per tile
#define OFF_AH 0
#define OFF_AL (1 * TILE_B)
#define OFF_BH (2 * TILE_B)
#define OFF_BL (3 * TILE_B)
#define STAGE  (4 * TILE_B)     // 40960
#define SMEM_DYN (2 * STAGE)    // 81920
#define NCHUNK 32               // 1024 / 32

__global__ void __launch_bounds__(256) gemm_kernel(float* __restrict__ out) {
    extern __shared__ __align__(128) char smem[];
    const uint32_t sbase = smem_u32(smem);

    const int b      = blockIdx.z;
    const int i_base = blockIdx.x * 128;
    const int s_base = blockIdx.y * 128;
    const int tid  = threadIdx.x;
    const int wid  = tid >> 5;
    const int lane = tid & 31;
    const int wm = wid & 1;      // 2 m-groups of 64
    const int wn = wid >> 1;     // 4 n-groups of 32

    const char* gAh = (const char*)g_eh + ((size_t)b * SS + s_base) * DD * 2;
    const char* gAl = (const char*)g_el + ((size_t)b * SS + s_base) * DD * 2;
    const char* gBh = (const char*)g_ch + ((size_t)b * DD + i_base) * DD * 2;
    const char* gBl = (const char*)g_cl + ((size_t)b * DD + i_base) * DD * 2;

    // loader mapping: per tile 512 16B-chunks (128 rows x 4)
    const int l_row0 = tid >> 2, l_c0 = tid & 3;
    const int l_row1 = (tid + 256) >> 2, l_c1 = tid & 3;  // (tid+256)&3 == tid&3

    // ldmatrix lane offsets (bytes, relative to tile base)
    const uint32_t a_lane = (uint32_t)(wm * 64 + (lane & 15)) * ROWB + (lane >> 4) * 16;
    const uint32_t b_lane = (uint32_t)(wn * 32 + (lane & 7) + 8 * (lane >> 4)) * ROWB
                          + ((lane >> 3) & 1) * 16;

    float acc[4][4][4];
    #pragma unroll
    for (int mt = 0; mt < 4; mt++)
        #pragma unroll
        for (int nt = 0; nt < 4; nt++)
            #pragma unroll
            for (int j = 0; j < 4; j++) acc[mt][nt][j] = 0.f;

    // ---- pipelined load ----
    #define LOAD_STAGE(ST, KC) do {                                              \
        uint32_t sb_ = sbase + (ST) * STAGE;                                     \
        size_t koff_ = (size_t)(KC) * 64;                                        \
        uint32_t d0_ = (uint32_t)l_row0 * ROWB + l_c0 * 16;                      \
        size_t  s0_ = (size_t)l_row0 * 2048 + koff_ + l_c0 * 16;                 \
        uint32_t d1_ = (uint32_t)l_row1 * ROWB + l_c1 * 16;                      \
        size_t  s1_ = (size_t)l_row1 * 2048 + koff_ + l_c1 * 16;                 \
        cpasync16(sb_ + OFF_AH + d0_, gAh + s0_);                                \
        cpasync16(sb_ + OFF_AL + d0_, gAl + s0_);                                \
        cpasync16(sb_ + OFF_BH + d0_, gBh + s0_);                                \
        cpasync16(sb_ + OFF_BL + d0_, gBl + s0_);                                \
        cpasync16(sb_ + OFF_AH + d1_, gAh + s1_);                                \
        cpasync16(sb_ + OFF_AL + d1_, gAl + s1_);                                \
        cpasync16(sb_ + OFF_BH + d1_, gBh + s1_);                                \
        cpasync16(sb_ + OFF_BL + d1_, gBl + s1_);                                \
        asm volatile("cp.async.commit_group;");                                  \
    } while (0)

    LOAD_STAGE(0, 0);

    for (int c = 0; c < NCHUNK; c++) {
        if (c + 1 < NCHUNK) {
            LOAD_STAGE((c + 1) & 1, c + 1);
            asm volatile("cp.async.wait_group 1;" ::: "memory");
        } else {
            asm volatile("cp.async.wait_group 0;" ::: "memory");
        }
        __syncthreads();

        const uint32_t sb = sbase + (c & 1) * STAGE;
        #pragma unroll
        for (int kk = 0; kk < 2; kk++) {
            const uint32_t kb = kk * 32;
            uint32_t aH[4][4], aL[4][4], bH[2][4], bL[2][4];
            #pragma unroll
            for (int mt = 0; mt < 4; mt++)
                ldsm4(aH[mt], sb + OFF_AH + a_lane + mt * 16 * ROWB + kb);
            #pragma unroll
            for (int p = 0; p < 2; p++)
                ldsm4(bH[p], sb + OFF_BH + b_lane + p * 16 * ROWB + kb);
            #pragma unroll
            for (int p = 0; p < 2; p++)
                ldsm4(bL[p], sb + OFF_BL + b_lane + p * 16 * ROWB + kb);
            #pragma unroll
            for (int mt = 0; mt < 4; mt++)
                #pragma unroll
                for (int nt = 0; nt < 4; nt++)
                    mma16816(acc[mt][nt], aH[mt], &bH[nt >> 1][2 * (nt & 1)]);
            #pragma unroll
            for (int mt = 0; mt < 4; mt++)
                #pragma unroll
                for (int nt = 0; nt < 4; nt++)
                    mma16816(acc[mt][nt], aH[mt], &bL[nt >> 1][2 * (nt & 1)]);
            #pragma unroll
            for (int mt = 0; mt < 4; mt++)
                ldsm4(aL[mt], sb + OFF_AL + a_lane + mt * 16 * ROWB + kb);
            #pragma unroll
            for (int mt = 0; mt < 4; mt++)
                #pragma unroll
                for (int nt = 0; nt < 4; nt++)
                    mma16816(acc[mt][nt], aL[mt], &bH[nt >> 1][2 * (nt & 1)]);
        }
        __syncthreads();
    }

    // ---- epilogue: direct f32 stores ----
    #pragma unroll
    for (int mt = 0; mt < 4; mt++) {
        int r0 = s_base + wm * 64 + mt * 16 + (lane >> 2);
        float* p0 = out + ((size_t)b * SS + r0) * DD + i_base + wn * 32 + (lane & 3) * 2;
        float* p1 = p0 + (size_t)8 * DD;
        #pragma unroll
        for (int nt = 0; nt < 4; nt++) {
            *(float2*)(p0 + nt * 8) = make_float2(acc[mt][nt][0], acc[mt][nt][1]);
            *(float2*)(p1 + nt * 8) = make_float2(acc[mt][nt][2], acc[mt][nt][3]);
        }
    }
}

// ============================ launch ============================
extern "C" void kernel_launch(void* const* d_in, const int* in_sizes, int n_in,
                              void* d_out, int out_size) {
    const float* emb = (const float*)d_in[0];   // (32, 512, 1024) f32
    const float* asp = (const float*)d_in[1];   // (32, 1024) f32
    float* out = (float*)d_out;                 // (32, 512, 1024) f32

    cudaFuncSetAttribute(gemm_kernel, cudaFuncAttributeMaxDynamicSharedMemorySize, SMEM_DYN);

    anorm_kernel<<<BB, 256>>>(asp);
    esplit_kernel<<<dim3(SS, BB), 256>>>(emb);
    circ_kernel<<<dim3(DD, BB), 256>>>();
    gemm_kernel<<<dim3(DD / 128, SS / 128, BB), 256, SMEM_DYN>>>(out);
}

// round 4
// speedup vs baseline: 1.6759x; 1.2082x over previous
#include <cuda_runtime.h>
#include <cuda_bf16.h>
#include <cstdint>

#define BB 32
#define SS 512
#define DD 1024

// ---- device scratch (module-load allocated; no runtime allocs) ----
// interleaved layouts: [row][kc(32)][hi/lo][32 bf16]  (128B per kc per row)
__device__ unsigned short g_ei[(size_t)BB * SS * 2 * DD];   // 64 MB  E hi/lo interleaved
__device__ unsigned short g_ci[(size_t)BB * DD * 2 * DD];   // 128 MB circulant hi/lo interleaved
__device__ __nv_bfloat16 g_ah2[BB * 2 * DD];                // aspect hi, duplicated
__device__ __nv_bfloat16 g_al2[BB * 2 * DD];                // aspect lo, duplicated

// ============================ helpers ============================
__device__ __forceinline__ uint32_t smem_u32(const void* p) {
    uint32_t a;
    asm("{ .reg .u64 t; cvta.to.shared.u64 t, %1; cvt.u32.u64 %0, t; }" : "=r"(a) : "l"(p));
    return a;
}
__device__ __forceinline__ void cpasync16(uint32_t dst, const void* src) {
    asm volatile("cp.async.cg.shared.global [%0], [%1], 16;" :: "r"(dst), "l"(src));
}
__device__ __forceinline__ void ldsm4(uint32_t* r, uint32_t a) {
    asm volatile("ldmatrix.sync.aligned.m8n8.x4.shared.b16 {%0,%1,%2,%3}, [%4];"
                 : "=r"(r[0]), "=r"(r[1]), "=r"(r[2]), "=r"(r[3]) : "r"(a));
}
__device__ __forceinline__ void mma16816(float* c, const uint32_t* a, const uint32_t* b) {
    asm volatile(
        "mma.sync.aligned.m16n8k16.row.col.f32.bf16.bf16.f32 "
        "{%0,%1,%2,%3}, {%4,%5,%6,%7}, {%8,%9}, {%0,%1,%2,%3};"
        : "+f"(c[0]), "+f"(c[1]), "+f"(c[2]), "+f"(c[3])
        : "r"(a[0]), "r"(a[1]), "r"(a[2]), "r"(a[3]), "r"(b[0]), "r"(b[1]));
}

// ============================ prep kernels ============================
__global__ void anorm_kernel(const float* __restrict__ a) {
    int b = blockIdx.x, t = threadIdx.x;  // 256 threads
    float4 v = ((const float4*)(a + (size_t)b * DD))[t];
    float sum = v.x * v.x + v.y * v.y + v.z * v.z + v.w * v.w;
    #pragma unroll
    for (int o = 16; o; o >>= 1) sum += __shfl_xor_sync(0xffffffffu, sum, o);
    __shared__ float ws[8];
    __shared__ float s_inv;
    if ((t & 31) == 0) ws[t >> 5] = sum;
    __syncthreads();
    if (t == 0) {
        float tot = 0.f;
        #pragma unroll
        for (int i = 0; i < 8; i++) tot += ws[i];
        s_inv = (tot > 0.f) ? rsqrtf(tot) : 0.f;
    }
    __syncthreads();
    float inv = s_inv;
    float n[4] = {v.x * inv, v.y * inv, v.z * inv, v.w * inv};
    #pragma unroll
    for (int j = 0; j < 4; j++) {
        __nv_bfloat16 h = __float2bfloat16(n[j]);
        __nv_bfloat16 l = __float2bfloat16(n[j] - __bfloat162float(h));
        size_t base = (size_t)b * 2 * DD + 4 * t + j;
        g_ah2[base] = h;  g_ah2[base + DD] = h;
        g_al2[base] = l;  g_al2[base + DD] = l;
    }
}

// E: normalize rows, split hi/lo, write interleaved [row][kc][2][32]
__global__ void esplit_kernel(const float* __restrict__ e) {
    int b = blockIdx.y, s = blockIdx.x, t = threadIdx.x;  // 256 threads
    size_t row = (size_t)b * SS + s;
    float4 v = ((const float4*)(e + row * DD))[t];
    float sum = v.x * v.x + v.y * v.y + v.z * v.z + v.w * v.w;
    #pragma unroll
    for (int o = 16; o; o >>= 1) sum += __shfl_xor_sync(0xffffffffu, sum, o);
    __shared__ float ws[8];
    __shared__ float s_inv;
    if ((t & 31) == 0) ws[t >> 5] = sum;
    __syncthreads();
    if (t == 0) {
        float tot = 0.f;
        #pragma unroll
        for (int i = 0; i < 8; i++) tot += ws[i];
        s_inv = (tot > 0.f) ? rsqrtf(tot) : 0.f;
    }
    __syncthreads();
    float inv = s_inv;
    float n[4] = {v.x * inv, v.y * inv, v.z * inv, v.w * inv};
    ushort4 ph, pl;
    unsigned short* hp = &ph.x;
    unsigned short* lp = &pl.x;
    #pragma unroll
    for (int j = 0; j < 4; j++) {
        __nv_bfloat16 h = __float2bfloat16(n[j]);
        __nv_bfloat16 l = __float2bfloat16(n[j] - __bfloat162float(h));
        hp[j] = __bfloat16_as_ushort(h);
        lp[j] = __bfloat16_as_ushort(l);
    }
    int kc = t >> 3, pos = (t & 7) * 4;
    size_t base = row * 2048 + (size_t)kc * 64 + pos;    // u16 units
    *((ushort4*)(g_ei + base)) = ph;
    *((ushort4*)(g_ei + base + 32)) = pl;
}

// circulant interleaved: c[b][n][kc][hi/lo][j] = a2[b][DD + kc*32 + j - n]
__global__ void circ_kernel() {
    int n = blockIdx.x, b = blockIdx.y, t = threadIdx.x;   // 256 threads
    int kc = t >> 3, pos = (t & 7) * 4;
    size_t src = (size_t)b * 2 * DD + DD - n + kc * 32 + pos;
    ushort4 ph, pl;
    unsigned short* hp = &ph.x;
    unsigned short* lp = &pl.x;
    #pragma unroll
    for (int j = 0; j < 4; j++) {
        hp[j] = __bfloat16_as_ushort(g_ah2[src + j]);
        lp[j] = __bfloat16_as_ushort(g_al2[src + j]);
    }
    size_t base = ((size_t)b * DD + n) * 2048 + (size_t)kc * 64 + pos;
    *((ushort4*)(g_ci + base)) = ph;
    *((ushort4*)(g_ci + base + 32)) = pl;
}

// ============================ GEMM kernel ============================
// out[b, s_base+m, i_base+n] = sum_k E[m][k] * C[n][k]   (3-way bf16 split)
// CTA 128x128, 256 thr (8 warps, warp 64x32), k-chunk 32, 3-stage cp.async ring.
#define ROWB 144                         // 128B payload [hi64|lo64] + 16B pad
#define STG (256 * ROWB)                 // 36864 B per stage (A rows 0-127, B rows 128-255)
#define NSTAGE 3
#define SMEM_DYN (NSTAGE * STG)          // 110592
#define NCHUNK 32
#define B_OFF (128 * ROWB)

__global__ void __launch_bounds__(256, 2) gemm_kernel(float* __restrict__ out) {
    extern __shared__ __align__(128) char smem[];
    const uint32_t sbase = smem_u32(smem);

    const int b      = blockIdx.z;
    const int i_base = blockIdx.x * 128;
    const int s_base = blockIdx.y * 128;
    const int tid  = threadIdx.x;
    const int wid  = tid >> 5;
    const int lane = tid & 31;
    const int wm = wid & 1;
    const int wn = wid >> 1;

    // loader: thread t owns one smem row (A row t, or B row t-128); 128B per chunk
    const unsigned short* gsrc = (tid < 128)
        ? g_ei + ((size_t)b * SS + s_base + tid) * 2048
        : g_ci + ((size_t)b * DD + i_base + (tid - 128)) * 2048;
    const uint32_t drow = sbase + (uint32_t)tid * ROWB;

    // ldmatrix lane offsets (relative to stage base)
    const uint32_t a_lane = (uint32_t)(wm * 64 + (lane & 15)) * ROWB + (lane >> 4) * 16;
    const uint32_t b_lane = B_OFF + (uint32_t)(wn * 32 + (lane & 7) + 8 * (lane >> 4)) * ROWB
                          + ((lane >> 3) & 1) * 16;

    float acc[4][4][4];
    #pragma unroll
    for (int mt = 0; mt < 4; mt++)
        #pragma unroll
        for (int nt = 0; nt < 4; nt++)
            #pragma unroll
            for (int j = 0; j < 4; j++) acc[mt][nt][j] = 0.f;

    #define LOAD_STAGE(ST, KC) do {                                    \
        uint32_t d_ = drow + (ST) * STG;                               \
        const char* s_ = (const char*)(gsrc + (size_t)(KC) * 64);      \
        cpasync16(d_ +   0, s_ +   0);  cpasync16(d_ +  16, s_ +  16); \
        cpasync16(d_ +  32, s_ +  32);  cpasync16(d_ +  48, s_ +  48); \
        cpasync16(d_ +  64, s_ +  64);  cpasync16(d_ +  80, s_ +  80); \
        cpasync16(d_ +  96, s_ +  96);  cpasync16(d_ + 112, s_ + 112); \
        asm volatile("cp.async.commit_group;");                        \
    } while (0)

    LOAD_STAGE(0, 0);
    LOAD_STAGE(1, 1);

    int stage = 0;
    for (int c = 0; c < NCHUNK; c++) {
        if (c < NCHUNK - 1)
            asm volatile("cp.async.wait_group 1;" ::: "memory");
        else
            asm volatile("cp.async.wait_group 0;" ::: "memory");
        __syncthreads();

        if (c + 2 < NCHUNK) {
            int nst = stage + 2; if (nst >= NSTAGE) nst -= NSTAGE;
            LOAD_STAGE(nst, c + 2);
        }

        const uint32_t sb = sbase + stage * STG;
        #pragma unroll
        for (int kk = 0; kk < 2; kk++) {
            const uint32_t kb = kk * 32;
            uint32_t aH[4][4], aL[4][4], bH[2][4], bL[2][4];
            #pragma unroll
            for (int mt = 0; mt < 4; mt++)
                ldsm4(aH[mt], sb + a_lane + mt * 16 * ROWB + kb);
            #pragma unroll
            for (int p = 0; p < 2; p++)
                ldsm4(bH[p], sb + b_lane + p * 16 * ROWB + kb);
            #pragma unroll
            for (int p = 0; p < 2; p++)
                ldsm4(bL[p], sb + b_lane + p * 16 * ROWB + 64 + kb);
            #pragma unroll
            for (int mt = 0; mt < 4; mt++)
                #pragma unroll
                for (int nt = 0; nt < 4; nt++)
                    mma16816(acc[mt][nt], aH[mt], &bH[nt >> 1][2 * (nt & 1)]);
            #pragma unroll
            for (int mt = 0; mt < 4; mt++)
                #pragma unroll
                for (int nt = 0; nt < 4; nt++)
                    mma16816(acc[mt][nt], aH[mt], &bL[nt >> 1][2 * (nt & 1)]);
            #pragma unroll
            for (int mt = 0; mt < 4; mt++)
                ldsm4(aL[mt], sb + a_lane + mt * 16 * ROWB + 64 + kb);
            #pragma unroll
            for (int mt = 0; mt < 4; mt++)
                #pragma unroll
                for (int nt = 0; nt < 4; nt++)
                    mma16816(acc[mt][nt], aL[mt], &bH[nt >> 1][2 * (nt & 1)]);
        }
        stage = (stage + 1 == NSTAGE) ? 0 : stage + 1;
    }

    // ---- epilogue: direct f32 stores ----
    #pragma unroll
    for (int mt = 0; mt < 4; mt++) {
        int r0 = s_base + wm * 64 + mt * 16 + (lane >> 2);
        float* p0 = out + ((size_t)b * SS + r0) * DD + i_base + wn * 32 + (lane & 3) * 2;
        float* p1 = p0 + (size_t)8 * DD;
        #pragma unroll
        for (int nt = 0; nt < 4; nt++) {
            *(float2*)(p0 + nt * 8) = make_float2(acc[mt][nt][0], acc[mt][nt][1]);
            *(float2*)(p1 + nt * 8) = make_float2(acc[mt][nt][2], acc[mt][nt][3]);
        }
    }
}

// ============================ launch ============================
extern "C" void kernel_launch(void* const* d_in, const int* in_sizes, int n_in,
                              void* d_out, int out_size) {
    const float* emb = (const float*)d_in[0];   // (32, 512, 1024) f32
    const float* asp = (const float*)d_in[1];   // (32, 1024) f32
    float* out = (float*)d_out;                 // (32, 512, 1024) f32

    cudaFuncSetAttribute(gemm_kernel, cudaFuncAttributeMaxDynamicSharedMemorySize, SMEM_DYN);

    anorm_kernel<<<BB, 256>>>(asp);
    esplit_kernel<<<dim3(SS, BB), 256>>>(emb);
    circ_kernel<<<dim3(DD, BB), 256>>>();
    gemm_kernel<<<dim3(DD / 128, SS / 128, BB), 256, SMEM_DYN>>>(out);
}

// round 5
// speedup vs baseline: 2.0877x; 1.2457x over previous
#include <cuda_runtime.h>
#include <cuda_bf16.h>
#include <cstdint>

#define BB 32
#define SS 512
#define DD 1024

// ---- device scratch (module-load allocated; no runtime allocs) ----
// interleaved layouts: [row][kc(32)][hi/lo][32 bf16]  (128B per kc per row)
__device__ unsigned short g_ei[(size_t)BB * SS * 2 * DD];   // 64 MB  E hi/lo interleaved
__device__ unsigned short g_ci[(size_t)BB * DD * 2 * DD];   // 128 MB circulant hi/lo interleaved
__device__ __nv_bfloat16 g_ah2[BB * 2 * DD];                // aspect hi, duplicated
__device__ __nv_bfloat16 g_al2[BB * 2 * DD];                // aspect lo, duplicated

// ============================ helpers ============================
__device__ __forceinline__ uint32_t smem_u32(const void* p) {
    uint32_t a;
    asm("{ .reg .u64 t; cvta.to.shared.u64 t, %1; cvt.u32.u64 %0, t; }" : "=r"(a) : "l"(p));
    return a;
}
__device__ __forceinline__ void cpasync16(uint32_t dst, const void* src) {
    asm volatile("cp.async.cg.shared.global [%0], [%1], 16;" :: "r"(dst), "l"(src));
}
__device__ __forceinline__ void ldsm4(uint32_t* r, uint32_t a) {
    asm volatile("ldmatrix.sync.aligned.m8n8.x4.shared.b16 {%0,%1,%2,%3}, [%4];"
                 : "=r"(r[0]), "=r"(r[1]), "=r"(r[2]), "=r"(r[3]) : "r"(a));
}
__device__ __forceinline__ void mma16816(float* c, const uint32_t* a, const uint32_t* b) {
    asm volatile(
        "mma.sync.aligned.m16n8k16.row.col.f32.bf16.bf16.f32 "
        "{%0,%1,%2,%3}, {%4,%5,%6,%7}, {%8,%9}, {%0,%1,%2,%3};"
        : "+f"(c[0]), "+f"(c[1]), "+f"(c[2]), "+f"(c[3])
        : "r"(a[0]), "r"(a[1]), "r"(a[2]), "r"(a[3]), "r"(b[0]), "r"(b[1]));
}

// ============================ prep kernels ============================
__global__ void anorm_kernel(const float* __restrict__ a) {
    int b = blockIdx.x, t = threadIdx.x;  // 256 threads
    float4 v = ((const float4*)(a + (size_t)b * DD))[t];
    float sum = v.x * v.x + v.y * v.y + v.z * v.z + v.w * v.w;
    #pragma unroll
    for (int o = 16; o; o >>= 1) sum += __shfl_xor_sync(0xffffffffu, sum, o);
    __shared__ float ws[8];
    __shared__ float s_inv;
    if ((t & 31) == 0) ws[t >> 5] = sum;
    __syncthreads();
    if (t == 0) {
        float tot = 0.f;
        #pragma unroll
        for (int i = 0; i < 8; i++) tot += ws[i];
        s_inv = (tot > 0.f) ? rsqrtf(tot) : 0.f;
    }
    __syncthreads();
    float inv = s_inv;
    float n[4] = {v.x * inv, v.y * inv, v.z * inv, v.w * inv};
    #pragma unroll
    for (int j = 0; j < 4; j++) {
        __nv_bfloat16 h = __float2bfloat16(n[j]);
        __nv_bfloat16 l = __float2bfloat16(n[j] - __bfloat162float(h));
        size_t base = (size_t)b * 2 * DD + 4 * t + j;
        g_ah2[base] = h;  g_ah2[base + DD] = h;
        g_al2[base] = l;  g_al2[base + DD] = l;
    }
}

// E: normalize rows, split hi/lo, write interleaved [row][kc][2][32]
__global__ void esplit_kernel(const float* __restrict__ e) {
    int b = blockIdx.y, s = blockIdx.x, t = threadIdx.x;  // 256 threads
    size_t row = (size_t)b * SS + s;
    float4 v = ((const float4*)(e + row * DD))[t];
    float sum = v.x * v.x + v.y * v.y + v.z * v.z + v.w * v.w;
    #pragma unroll
    for (int o = 16; o; o >>= 1) sum += __shfl_xor_sync(0xffffffffu, sum, o);
    __shared__ float ws[8];
    __shared__ float s_inv;
    if ((t & 31) == 0) ws[t >> 5] = sum;
    __syncthreads();
    if (t == 0) {
        float tot = 0.f;
        #pragma unroll
        for (int i = 0; i < 8; i++) tot += ws[i];
        s_inv = (tot > 0.f) ? rsqrtf(tot) : 0.f;
    }
    __syncthreads();
    float inv = s_inv;
    float n[4] = {v.x * inv, v.y * inv, v.z * inv, v.w * inv};
    ushort4 ph, pl;
    unsigned short* hp = &ph.x;
    unsigned short* lp = &pl.x;
    #pragma unroll
    for (int j = 0; j < 4; j++) {
        __nv_bfloat16 h = __float2bfloat16(n[j]);
        __nv_bfloat16 l = __float2bfloat16(n[j] - __bfloat162float(h));
        hp[j] = __bfloat16_as_ushort(h);
        lp[j] = __bfloat16_as_ushort(l);
    }
    int kc = t >> 3, pos = (t & 7) * 4;
    size_t base = row * 2048 + (size_t)kc * 64 + pos;    // u16 units
    *((ushort4*)(g_ei + base)) = ph;
    *((ushort4*)(g_ei + base + 32)) = pl;
}

// circulant interleaved: c[b][n][kc][hi/lo][j] = a2[b][DD + kc*32 + j - n]
__global__ void circ_kernel() {
    int n = blockIdx.x, b = blockIdx.y, t = threadIdx.x;   // 256 threads
    int kc = t >> 3, pos = (t & 7) * 4;
    size_t src = (size_t)b * 2 * DD + DD - n + kc * 32 + pos;
    ushort4 ph, pl;
    unsigned short* hp = &ph.x;
    unsigned short* lp = &pl.x;
    #pragma unroll
    for (int j = 0; j < 4; j++) {
        hp[j] = __bfloat16_as_ushort(g_ah2[src + j]);
        lp[j] = __bfloat16_as_ushort(g_al2[src + j]);
    }
    size_t base = ((size_t)b * DD + n) * 2048 + (size_t)kc * 64 + pos;
    *((ushort4*)(g_ci + base)) = ph;
    *((ushort4*)(g_ci + base + 32)) = pl;
}

// ============================ GEMM kernel ============================
// out[b, s_base+m, i_base+n] = sum_k E[m][k] * C[n][k]   (3-way bf16 split)
// CTA 256x128, 512 thr (16 warps, warp 64x32), k-chunk 64, 2-stage ring.
#define ROWB 272                 // 256B payload [kc0:hi|lo][kc1:hi|lo] + 16B pad
#define NROWS 384                // A rows 0-255, B rows 256-383
#define STG (NROWS * ROWB)       // 104448 B per stage
#define SMEM_DYN (2 * STG)       // 208896
#define NCHUNK 16                // 1024 / 64
#define B_OFF (256 * ROWB)

__global__ void __launch_bounds__(512, 1) gemm_kernel(float* __restrict__ out) {
    extern __shared__ __align__(128) char smem[];
    const uint32_t sbase = smem_u32(smem);

    const int b      = blockIdx.z;
    const int i_base = blockIdx.x * 128;
    const int s_base = blockIdx.y * 256;
    const int tid  = threadIdx.x;
    const int wid  = tid >> 5;
    const int lane = tid & 31;
    const int wm = wid & 3;      // 4 m-groups of 64
    const int wn = wid >> 2;     // 4 n-groups of 32

    // loader: thread covers rows r0+32*i (i=0..11), fixed 16B segment t&15.
    // i<8 -> A row (r0+32i); i>=8 -> B row (r0+32(i-8)). Row = 4096B in gmem.
    const int r0  = tid >> 4;
    const int seg = tid & 15;
    const char* pA = (const char*)g_ei + ((size_t)b * SS + s_base + r0) * 4096 + seg * 16;
    const char* pB = (const char*)g_ci + ((size_t)b * DD + i_base + r0) * 4096 + seg * 16;
    const uint32_t drowA = sbase + (uint32_t)r0 * ROWB + seg * 16;
    const uint32_t drowB = sbase + B_OFF + (uint32_t)r0 * ROWB + seg * 16;

    // ldmatrix lane offsets (relative to stage base; add kbyte per step)
    const uint32_t a_lane = (uint32_t)(wm * 64 + (lane & 15)) * ROWB + (lane >> 4) * 16;
    const uint32_t b_lane = B_OFF + (uint32_t)(wn * 32 + (lane & 7) + 8 * (lane >> 4)) * ROWB
                          + ((lane >> 3) & 1) * 16;

    float acc[4][4][4];
    #pragma unroll
    for (int mt = 0; mt < 4; mt++)
        #pragma unroll
        for (int nt = 0; nt < 4; nt++)
            #pragma unroll
            for (int j = 0; j < 4; j++) acc[mt][nt][j] = 0.f;

    #define LOAD_STAGE(ST, KC) do {                                     \
        uint32_t so_ = (ST) * STG;                                      \
        size_t go_ = (size_t)(KC) * 256;                                \
        _Pragma("unroll")                                               \
        for (int i_ = 0; i_ < 8; i_++)                                  \
            cpasync16(drowA + so_ + i_ * (32 * ROWB),                   \
                      pA + go_ + (size_t)i_ * (32 * 4096));             \
        _Pragma("unroll")                                               \
        for (int i_ = 0; i_ < 4; i_++)                                  \
            cpasync16(drowB + so_ + i_ * (32 * ROWB),                   \
                      pB + go_ + (size_t)i_ * (32 * 4096));             \
        asm volatile("cp.async.commit_group;");                         \
    } while (0)

    LOAD_STAGE(0, 0);

    for (int c = 0; c < NCHUNK; c++) {
        asm volatile("cp.async.wait_group 0;" ::: "memory");
        __syncthreads();

        const int stg = c & 1;
        const uint32_t sb = sbase + stg * STG;

        // prefetch next chunk into the other stage (overlaps compute below)
        if (c + 1 < NCHUNK) LOAD_STAGE(stg ^ 1, c + 1);

        #pragma unroll
        for (int kk = 0; kk < 4; kk++) {
            // hi at (kk>>1)*128 + (kk&1)*32 ; lo at +64
            const uint32_t kb = (uint32_t)((kk >> 1) * 128 + (kk & 1) * 32);
            uint32_t aH[4][4], aL[4][4], bH[2][4], bL[2][4];
            #pragma unroll
            for (int mt = 0; mt < 4; mt++)
                ldsm4(aH[mt], sb + a_lane + mt * 16 * ROWB + kb);
            #pragma unroll
            for (int p = 0; p < 2; p++)
                ldsm4(bH[p], sb + b_lane + p * 16 * ROWB + kb);
            #pragma unroll
            for (int p = 0; p < 2; p++)
                ldsm4(bL[p], sb + b_lane + p * 16 * ROWB + kb + 64);
            #pragma unroll
            for (int mt = 0; mt < 4; mt++)
                #pragma unroll
                for (int nt = 0; nt < 4; nt++)
                    mma16816(acc[mt][nt], aH[mt], &bH[nt >> 1][2 * (nt & 1)]);
            #pragma unroll
            for (int mt = 0; mt < 4; mt++)
                #pragma unroll
                for (int nt = 0; nt < 4; nt++)
                    mma16816(acc[mt][nt], aH[mt], &bL[nt >> 1][2 * (nt & 1)]);
            #pragma unroll
            for (int mt = 0; mt < 4; mt++)
                ldsm4(aL[mt], sb + a_lane + mt * 16 * ROWB + kb + 64);
            #pragma unroll
            for (int mt = 0; mt < 4; mt++)
                #pragma unroll
                for (int nt = 0; nt < 4; nt++)
                    mma16816(acc[mt][nt], aL[mt], &bH[nt >> 1][2 * (nt & 1)]);
        }
    }

    // ---- epilogue: direct f32 stores ----
    #pragma unroll
    for (int mt = 0; mt < 4; mt++) {
        int rr = s_base + wm * 64 + mt * 16 + (lane >> 2);
        float* p0 = out + ((size_t)b * SS + rr) * DD + i_base + wn * 32 + (lane & 3) * 2;
        float* p1 = p0 + (size_t)8 * DD;
        #pragma unroll
        for (int nt = 0; nt < 4; nt++) {
            *(float2*)(p0 + nt * 8) = make_float2(acc[mt][nt][0], acc[mt][nt][1]);
            *(float2*)(p1 + nt * 8) = make_float2(acc[mt][nt][2], acc[mt][nt][3]);
        }
    }
}

// ============================ launch ============================
extern "C" void kernel_launch(void* const* d_in, const int* in_sizes, int n_in,
                              void* d_out, int out_size) {
    const float* emb = (const float*)d_in[0];   // (32, 512, 1024) f32
    const float* asp = (const float*)d_in[1];   // (32, 1024) f32
    float* out = (float*)d_out;                 // (32, 512, 1024) f32

    cudaFuncSetAttribute(gemm_kernel, cudaFuncAttributeMaxDynamicSharedMemorySize, SMEM_DYN);

    anorm_kernel<<<BB, 256>>>(asp);
    esplit_kernel<<<dim3(SS, BB), 256>>>(emb);
    circ_kernel<<<dim3(DD, BB), 256>>>();
    gemm_kernel<<<dim3(DD / 128, SS / 256, BB), 512, SMEM_DYN>>>(out);
}

// round 6
// speedup vs baseline: 2.3750x; 1.1377x over previous
#include <cuda_runtime.h>
#include <cuda_bf16.h>
#include <cstdint>

#define BB 32
#define SS 512
#define DD 1024

// ---- device scratch (module-load allocated; no runtime allocs) ----
// E interleaved: [row][kc(32)][hi/lo][32 bf16]  (128B per kc per row)
__device__ unsigned short g_ei[(size_t)BB * SS * 2 * DD];   // 64 MB
// aspect copies: [b][buf(4: hi-p0, hi-p1, lo-p0, lo-p1)][2048 u16]
// buf p semantics: buf_p[x] = a2[x+p], a2[y] = a_norm[y mod 1024], y in [0,2048]
__device__ unsigned short g_asp[BB * 4 * 2048];             // 512 KB

// ============================ helpers ============================
__device__ __forceinline__ uint32_t smem_u32(const void* p) {
    uint32_t a;
    asm("{ .reg .u64 t; cvta.to.shared.u64 t, %1; cvt.u32.u64 %0, t; }" : "=r"(a) : "l"(p));
    return a;
}
__device__ __forceinline__ void cpasync16(uint32_t dst, const void* src) {
    asm volatile("cp.async.cg.shared.global [%0], [%1], 16;" :: "r"(dst), "l"(src));
}
__device__ __forceinline__ void ldsm4(uint32_t* r, uint32_t a) {
    asm volatile("ldmatrix.sync.aligned.m8n8.x4.shared.b16 {%0,%1,%2,%3}, [%4];"
                 : "=r"(r[0]), "=r"(r[1]), "=r"(r[2]), "=r"(r[3]) : "r"(a));
}
__device__ __forceinline__ void mma16816(float* c, const uint32_t* a, const uint32_t* b) {
    asm volatile(
        "mma.sync.aligned.m16n8k16.row.col.f32.bf16.bf16.f32 "
        "{%0,%1,%2,%3}, {%4,%5,%6,%7}, {%8,%9}, {%0,%1,%2,%3};"
        : "+f"(c[0]), "+f"(c[1]), "+f"(c[2]), "+f"(c[3])
        : "r"(a[0]), "r"(a[1]), "r"(a[2]), "r"(a[3]), "r"(b[0]), "r"(b[1]));
}
__device__ __forceinline__ uint32_t lds32(uint32_t a) {
    uint32_t v;
    asm volatile("ld.shared.b32 %0, [%1];" : "=r"(v) : "r"(a));
    return v;
}
__device__ __forceinline__ void sts32(uint32_t a, uint32_t v) {
    asm volatile("st.shared.b32 [%0], %1;" :: "r"(a), "r"(v));
}

// ============================ prep kernels ============================
// normalize aspect, split hi/lo bf16, write 4 parity copies
__global__ void anorm_kernel(const float* __restrict__ a) {
    int b = blockIdx.x, t = threadIdx.x;  // 256 threads
    float4 v = ((const float4*)(a + (size_t)b * DD))[t];
    float sum = v.x * v.x + v.y * v.y + v.z * v.z + v.w * v.w;
    #pragma unroll
    for (int o = 16; o; o >>= 1) sum += __shfl_xor_sync(0xffffffffu, sum, o);
    __shared__ float ws[8];
    __shared__ float s_inv;
    if ((t & 31) == 0) ws[t >> 5] = sum;
    __syncthreads();
    if (t == 0) {
        float tot = 0.f;
        #pragma unroll
        for (int i = 0; i < 8; i++) tot += ws[i];
        s_inv = (tot > 0.f) ? rsqrtf(tot) : 0.f;
    }
    __syncthreads();
    float inv = s_inv;
    float n[4] = {v.x * inv, v.y * inv, v.z * inv, v.w * inv};
    unsigned short* base = g_asp + b * 4 * 2048;
    #pragma unroll
    for (int j = 0; j < 4; j++) {
        __nv_bfloat16 h = __float2bfloat16(n[j]);
        __nv_bfloat16 l = __float2bfloat16(n[j] - __bfloat162float(h));
        unsigned short hu = __bfloat16_as_ushort(h);
        unsigned short lu = __bfloat16_as_ushort(l);
        int e = 4 * t + j;
        // hi-p0 (buf 0): x = e, e+1024 ; hi-p1 (buf 1): x = (e+1023), (e+2047)&2047
        base[e] = hu;                      base[e + 1024] = hu;
        base[2048 + ((e + 1023) & 2047)] = hu;
        base[2048 + ((e + 2047) & 2047)] = hu;
        base[4096 + e] = lu;               base[4096 + e + 1024] = lu;
        base[6144 + ((e + 1023) & 2047)] = lu;
        base[6144 + ((e + 2047) & 2047)] = lu;
    }
}

// E: normalize rows, split hi/lo, write interleaved [row][kc][2][32]
__global__ void esplit_kernel(const float* __restrict__ e) {
    int b = blockIdx.y, s = blockIdx.x, t = threadIdx.x;  // 256 threads
    size_t row = (size_t)b * SS + s;
    float4 v = ((const float4*)(e + row * DD))[t];
    float sum = v.x * v.x + v.y * v.y + v.z * v.z + v.w * v.w;
    #pragma unroll
    for (int o = 16; o; o >>= 1) sum += __shfl_xor_sync(0xffffffffu, sum, o);
    __shared__ float ws[8];
    __shared__ float s_inv;
    if ((t & 31) == 0) ws[t >> 5] = sum;
    __syncthreads();
    if (t == 0) {
        float tot = 0.f;
        #pragma unroll
        for (int i = 0; i < 8; i++) tot += ws[i];
        s_inv = (tot > 0.f) ? rsqrtf(tot) : 0.f;
    }
    __syncthreads();
    float inv = s_inv;
    float n[4] = {v.x * inv, v.y * inv, v.z * inv, v.w * inv};
    ushort4 ph, pl;
    unsigned short* hp = &ph.x;
    unsigned short* lp = &pl.x;
    #pragma unroll
    for (int j = 0; j < 4; j++) {
        __nv_bfloat16 h = __float2bfloat16(n[j]);
        __nv_bfloat16 l = __float2bfloat16(n[j] - __bfloat162float(h));
        hp[j] = __bfloat16_as_ushort(h);
        lp[j] = __bfloat16_as_ushort(l);
    }
    int kc = t >> 3, pos = (t & 7) * 4;
    size_t base = row * 2048 + (size_t)kc * 64 + pos;    // u16 units
    *((ushort4*)(g_ei + base)) = ph;
    *((ushort4*)(g_ei + base + 32)) = pl;
}

// ============================ GEMM kernel ============================
// out[b, s_base+m, i_base+n] = sum_k E[m][k] * Circ[n][k]   (3-way bf16 split)
// CTA 256x128, 512 thr, k-chunk 64, 2-stage A ring, B built in smem from aspect.
#define ROWB 272                 // 256B payload + 16B pad
#define ASTG (256 * ROWB)        // 69632 per A stage
#define BSTG (128 * ROWB)        // 34816 per B buffer
#define OFF_B (2 * ASTG)         // 139264
#define OFF_ASP (OFF_B + 2 * BSTG)   // 208896
#define SMEM_DYN (OFF_ASP + 16384)   // 225280
#define NCHUNK 16                // 1024 / 64

__global__ void __launch_bounds__(512, 1) gemm_kernel(float* __restrict__ out) {
    extern __shared__ __align__(128) char smem[];
    const uint32_t sbase = smem_u32(smem);
    const uint32_t sB = sbase + OFF_B;
    const uint32_t sAsp = sbase + OFF_ASP;

    const int b      = blockIdx.z;
    const int i_base = blockIdx.x * 128;
    const int s_base = blockIdx.y * 256;
    const int tid  = threadIdx.x;
    const int wid  = tid >> 5;
    const int lane = tid & 31;
    const int wm = wid & 3;      // 4 m-groups of 64
    const int wn = wid >> 2;     // 4 n-groups of 32

    // A loader: thread covers rows r0+32*i (i=0..7), fixed 16B segment tid&15
    const int r0  = tid >> 4;
    const int seg = tid & 15;
    const char* pA = (const char*)g_ei + ((size_t)b * SS + s_base + r0) * 4096 + seg * 16;
    const uint32_t drowA = sbase + (uint32_t)r0 * ROWB + seg * 16;

    // ldmatrix lane offsets
    const uint32_t a_lane = (uint32_t)(wm * 64 + (lane & 15)) * ROWB + (lane >> 4) * 16;
    const uint32_t b_lane = (uint32_t)(wn * 32 + (lane & 7) + 8 * (lane >> 4)) * ROWB
                          + ((lane >> 3) & 1) * 16;

    // B build: this warp owns rows n0..n0+7 (split of the wn-group's 32 rows by wm)
    const int bn0 = wn * 32 + wm * 8;

    float acc[4][4][4];
    #pragma unroll
    for (int mt = 0; mt < 4; mt++)
        #pragma unroll
        for (int nt = 0; nt < 4; nt++)
            #pragma unroll
            for (int j = 0; j < 4; j++) acc[mt][nt][j] = 0.f;

    #define LOAD_A(ST, KC) do {                                         \
        uint32_t so_ = (ST) * ASTG;                                     \
        size_t go_ = (size_t)(KC) * 256;                                \
        _Pragma("unroll")                                               \
        for (int i_ = 0; i_ < 8; i_++)                                  \
            cpasync16(drowA + so_ + i_ * (32 * ROWB),                   \
                      pA + go_ + (size_t)i_ * (32 * 4096));             \
        asm volatile("cp.async.commit_group;");                         \
    } while (0)

    // build B rows for chunk CN into buffer CN&1; row layout [hi 128B | lo 128B]
    #define BUILD_B(CN) do {                                            \
        uint32_t bb_ = sB + ((CN) & 1) * BSTG;                          \
        int k0_ = (CN) * 64;                                            \
        _Pragma("unroll")                                               \
        for (int rr_ = 0; rr_ < 8; rr_++) {                             \
            int row_ = bn0 + rr_;                                       \
            int ig_ = i_base + row_;                                    \
            int p_ = ig_ & 1;                                           \
            uint32_t su_ = (uint32_t)((DD + k0_ - ig_ - p_) >> 1) * 4 + lane * 4; \
            uint32_t dst_ = bb_ + (uint32_t)row_ * ROWB + lane * 4;     \
            sts32(dst_, lds32(sAsp + p_ * 4096 + su_));                 \
            sts32(dst_ + 128, lds32(sAsp + (2 + p_) * 4096 + su_));     \
        }                                                               \
    } while (0)

    // ---- prologue: aspect copies + A(0) in one group ----
    {
        const char* pAsp = (const char*)(g_asp + b * 4 * 2048);
        cpasync16(sAsp + tid * 16, pAsp + tid * 16);
        cpasync16(sAsp + (tid + 512) * 16, pAsp + (size_t)(tid + 512) * 16);
    }
    LOAD_A(0, 0);   // includes commit for the whole group

    asm volatile("cp.async.wait_group 0;" ::: "memory");
    __syncthreads();
    BUILD_B(0);

    for (int c = 0; c < NCHUNK; c++) {
        if (c > 0) {
            asm volatile("cp.async.wait_group 0;" ::: "memory");
            __syncthreads();
        }
        if (c + 1 < NCHUNK) LOAD_A((c + 1) & 1, c + 1);

        const uint32_t sa = sbase + (c & 1) * ASTG;
        const uint32_t sb = sB + (c & 1) * BSTG;

        #pragma unroll
        for (int kk = 0; kk < 4; kk++) {
            // A layout per 256B: [kc0 hi64|kc0 lo64|kc1 hi64|kc1 lo64]
            const uint32_t akb = (uint32_t)((kk >> 1) * 128 + (kk & 1) * 32);
            // B layout per 256B: [hi 128 | lo 128]
            const uint32_t bkb = (uint32_t)(kk * 32);
            uint32_t aH[4][4], aL[4][4], bH[2][4], bL[2][4];
            #pragma unroll
            for (int mt = 0; mt < 4; mt++)
                ldsm4(aH[mt], sa + a_lane + mt * 16 * ROWB + akb);
            #pragma unroll
            for (int p = 0; p < 2; p++)
                ldsm4(bH[p], sb + b_lane + p * 16 * ROWB + bkb);
            #pragma unroll
            for (int p = 0; p < 2; p++)
                ldsm4(bL[p], sb + b_lane + p * 16 * ROWB + bkb + 128);
            #pragma unroll
            for (int mt = 0; mt < 4; mt++)
                #pragma unroll
                for (int nt = 0; nt < 4; nt++)
                    mma16816(acc[mt][nt], aH[mt], &bH[nt >> 1][2 * (nt & 1)]);
            #pragma unroll
            for (int mt = 0; mt < 4; mt++)
                #pragma unroll
                for (int nt = 0; nt < 4; nt++)
                    mma16816(acc[mt][nt], aH[mt], &bL[nt >> 1][2 * (nt & 1)]);
            #pragma unroll
            for (int mt = 0; mt < 4; mt++)
                ldsm4(aL[mt], sa + a_lane + mt * 16 * ROWB + akb + 64);
            #pragma unroll
            for (int mt = 0; mt < 4; mt++)
                #pragma unroll
                for (int nt = 0; nt < 4; nt++)
                    mma16816(acc[mt][nt], aL[mt], &bH[nt >> 1][2 * (nt & 1)]);
        }

        if (c + 1 < NCHUNK) BUILD_B(c + 1);
    }

    // ---- epilogue: direct f32 stores ----
    #pragma unroll
    for (int mt = 0; mt < 4; mt++) {
        int rr = s_base + wm * 64 + mt * 16 + (lane >> 2);
        float* p0 = out + ((size_t)b * SS + rr) * DD + i_base + wn * 32 + (lane & 3) * 2;
        float* p1 = p0 + (size_t)8 * DD;
        #pragma unroll
        for (int nt = 0; nt < 4; nt++) {
            *(float2*)(p0 + nt * 8) = make_float2(acc[mt][nt][0], acc[mt][nt][1]);
            *(float2*)(p1 + nt * 8) = make_float2(acc[mt][nt][2], acc[mt][nt][3]);
        }
    }
}

// ============================ launch ============================
extern "C" void kernel_launch(void* const* d_in, const int* in_sizes, int n_in,
                              void* d_out, int out_size) {
    const float* emb = (const float*)d_in[0];   // (32, 512, 1024) f32
    const float* asp = (const float*)d_in[1];   // (32, 1024) f32
    float* out = (float*)d_out;                 // (32, 512, 1024) f32

    cudaFuncSetAttribute(gemm_kernel, cudaFuncAttributeMaxDynamicSharedMemorySize, SMEM_DYN);

    anorm_kernel<<<BB, 256>>>(asp);
    esplit_kernel<<<dim3(SS, BB), 256>>>(emb);
    gemm_kernel<<<dim3(DD / 128, SS / 256, BB), 512, SMEM_DYN>>>(out);
}

// round 7
// speedup vs baseline: 2.4598x; 1.0357x over previous
#include <cuda_runtime.h>
#include <cuda_bf16.h>
#include <cstdint>

#define BB 32
#define SS 512
#define DD 1024

// ---- device scratch (module-load allocated; no runtime allocs) ----
// E interleaved: [row][kc(32)][hi/lo][32 bf16]  (128B per kc per row)
__device__ unsigned short g_ei[(size_t)BB * SS * 2 * DD];   // 64 MB
// aspect copies: [b][buf(4: hi-p0, hi-p1, lo-p0, lo-p1)][2048 u16]
__device__ unsigned short g_asp[BB * 4 * 2048];             // 512 KB

// ============================ helpers ============================
__device__ __forceinline__ uint32_t smem_u32(const void* p) {
    uint32_t a;
    asm("{ .reg .u64 t; cvta.to.shared.u64 t, %1; cvt.u32.u64 %0, t; }" : "=r"(a) : "l"(p));
    return a;
}
__device__ __forceinline__ void cpasync16(uint32_t dst, const void* src) {
    asm volatile("cp.async.cg.shared.global [%0], [%1], 16;" :: "r"(dst), "l"(src));
}
__device__ __forceinline__ void ldsm4(uint32_t* r, uint32_t a) {
    asm volatile("ldmatrix.sync.aligned.m8n8.x4.shared.b16 {%0,%1,%2,%3}, [%4];"
                 : "=r"(r[0]), "=r"(r[1]), "=r"(r[2]), "=r"(r[3]) : "r"(a));
}
__device__ __forceinline__ void mma16816(float* c, const uint32_t* a, const uint32_t* b) {
    asm volatile(
        "mma.sync.aligned.m16n8k16.row.col.f32.bf16.bf16.f32 "
        "{%0,%1,%2,%3}, {%4,%5,%6,%7}, {%8,%9}, {%0,%1,%2,%3};"
        : "+f"(c[0]), "+f"(c[1]), "+f"(c[2]), "+f"(c[3])
        : "r"(a[0]), "r"(a[1]), "r"(a[2]), "r"(a[3]), "r"(b[0]), "r"(b[1]));
}
__device__ __forceinline__ uint32_t lds32(uint32_t a) {
    uint32_t v;
    asm volatile("ld.shared.b32 %0, [%1];" : "=r"(v) : "r"(a));
    return v;
}
__device__ __forceinline__ void sts32(uint32_t a, uint32_t v) {
    asm volatile("st.shared.b32 [%0], %1;" :: "r"(a), "r"(v));
}

// ============================ prep kernels ============================
// normalize aspect, split hi/lo bf16, write 4 parity copies
__global__ void anorm_kernel(const float* __restrict__ a) {
    int b = blockIdx.x, t = threadIdx.x;  // 256 threads
    float4 v = ((const float4*)(a + (size_t)b * DD))[t];
    float sum = v.x * v.x + v.y * v.y + v.z * v.z + v.w * v.w;
    #pragma unroll
    for (int o = 16; o; o >>= 1) sum += __shfl_xor_sync(0xffffffffu, sum, o);
    __shared__ float ws[8];
    __shared__ float s_inv;
    if ((t & 31) == 0) ws[t >> 5] = sum;
    __syncthreads();
    if (t == 0) {
        float tot = 0.f;
        #pragma unroll
        for (int i = 0; i < 8; i++) tot += ws[i];
        s_inv = (tot > 0.f) ? rsqrtf(tot) : 0.f;
    }
    __syncthreads();
    float inv = s_inv;
    float n[4] = {v.x * inv, v.y * inv, v.z * inv, v.w * inv};
    unsigned short* base = g_asp + b * 4 * 2048;
    #pragma unroll
    for (int j = 0; j < 4; j++) {
        __nv_bfloat16 h = __float2bfloat16(n[j]);
        __nv_bfloat16 l = __float2bfloat16(n[j] - __bfloat162float(h));
        unsigned short hu = __bfloat16_as_ushort(h);
        unsigned short lu = __bfloat16_as_ushort(l);
        int e = 4 * t + j;
        base[e] = hu;                      base[e + 1024] = hu;
        base[2048 + ((e + 1023) & 2047)] = hu;
        base[2048 + ((e + 2047) & 2047)] = hu;
        base[4096 + e] = lu;               base[4096 + e + 1024] = lu;
        base[6144 + ((e + 1023) & 2047)] = lu;
        base[6144 + ((e + 2047) & 2047)] = lu;
    }
}

// E: normalize rows, split hi/lo, write interleaved [row][kc][2][32]
__global__ void esplit_kernel(const float* __restrict__ e) {
    int b = blockIdx.y, s = blockIdx.x, t = threadIdx.x;  // 256 threads
    size_t row = (size_t)b * SS + s;
    float4 v = ((const float4*)(e + row * DD))[t];
    float sum = v.x * v.x + v.y * v.y + v.z * v.z + v.w * v.w;
    #pragma unroll
    for (int o = 16; o; o >>= 1) sum += __shfl_xor_sync(0xffffffffu, sum, o);
    __shared__ float ws[8];
    __shared__ float s_inv;
    if ((t & 31) == 0) ws[t >> 5] = sum;
    __syncthreads();
    if (t == 0) {
        float tot = 0.f;
        #pragma unroll
        for (int i = 0; i < 8; i++) tot += ws[i];
        s_inv = (tot > 0.f) ? rsqrtf(tot) : 0.f;
    }
    __syncthreads();
    float inv = s_inv;
    float n[4] = {v.x * inv, v.y * inv, v.z * inv, v.w * inv};
    ushort4 ph, pl;
    unsigned short* hp = &ph.x;
    unsigned short* lp = &pl.x;
    #pragma unroll
    for (int j = 0; j < 4; j++) {
        __nv_bfloat16 h = __float2bfloat16(n[j]);
        __nv_bfloat16 l = __float2bfloat16(n[j] - __bfloat162float(h));
        hp[j] = __bfloat16_as_ushort(h);
        lp[j] = __bfloat16_as_ushort(l);
    }
    int kc = t >> 3, pos = (t & 7) * 4;
    size_t base = row * 2048 + (size_t)kc * 64 + pos;    // u16 units
    *((ushort4*)(g_ei + base)) = ph;
    *((ushort4*)(g_ei + base + 32)) = pl;
}

// ============================ GEMM kernel ============================
// out[b, s_base+m, i_base+n] = sum_k E[m][k] * Circ[n][k]   (3-way bf16 split)
// CTA 256x128, 512 thr, k-chunk 64, 2-stage A ring, B built in smem from aspect.
#define ROWB 272                 // 256B payload + 16B pad
#define ASTG (256 * ROWB)        // 69632 per A stage
#define BSTG (128 * ROWB)        // 34816 per B buffer
#define OFF_B (2 * ASTG)         // 139264
#define OFF_ASP (OFF_B + 2 * BSTG)   // 208896
#define SMEM_DYN (OFF_ASP + 16384)   // 225280
#define NCHUNK 16                // 1024 / 64

__global__ void __launch_bounds__(512, 1) gemm_kernel(float* __restrict__ out) {
    extern __shared__ __align__(128) char smem[];
    const uint32_t sbase = smem_u32(smem);
    const uint32_t sB = sbase + OFF_B;
    const uint32_t sAsp = sbase + OFF_ASP;

    const int b      = blockIdx.z;
    const int i_base = blockIdx.x * 128;
    const int s_base = blockIdx.y * 256;
    const int tid  = threadIdx.x;
    const int wid  = tid >> 5;
    const int lane = tid & 31;
    const int wm = wid & 3;      // 4 m-groups of 64
    const int wn = wid >> 2;     // 4 n-groups of 32

    // A loader: thread covers rows r0+32*i (i=0..7), fixed 16B segment tid&15
    const int r0  = tid >> 4;
    const int seg = tid & 15;
    const char* pA = (const char*)g_ei + ((size_t)b * SS + s_base + r0) * 4096 + seg * 16;
    const uint32_t drowA = sbase + (uint32_t)r0 * ROWB + seg * 16;

    // ldmatrix lane offsets
    const uint32_t a_lane = (uint32_t)(wm * 64 + (lane & 15)) * ROWB + (lane >> 4) * 16;
    const uint32_t b_lane = (uint32_t)(wn * 32 + (lane & 7) + 8 * (lane >> 4)) * ROWB
                          + ((lane >> 3) & 1) * 16;

    // B build: this warp owns rows bn0..bn0+7
    const int bn0 = wn * 32 + wm * 8;

    float acc[4][4][4];
    #pragma unroll
    for (int mt = 0; mt < 4; mt++)
        #pragma unroll
        for (int nt = 0; nt < 4; nt++)
            #pragma unroll
            for (int j = 0; j < 4; j++) acc[mt][nt][j] = 0.f;

    #define LOAD_A(ST, KC) do {                                         \
        uint32_t so_ = (ST) * ASTG;                                     \
        size_t go_ = (size_t)(KC) * 256;                                \
        _Pragma("unroll")                                               \
        for (int i_ = 0; i_ < 8; i_++)                                  \
            cpasync16(drowA + so_ + i_ * (32 * ROWB),                   \
                      pA + go_ + (size_t)i_ * (32 * 4096));             \
        asm volatile("cp.async.commit_group;");                         \
    } while (0)

    // build 2 B rows (rr base RB) for chunk CN into buffer CN&1
    #define BUILD_B2(CN, RB) do {                                       \
        uint32_t bb_ = sB + ((CN) & 1) * BSTG;                          \
        int k0_ = (CN) * 64;                                            \
        _Pragma("unroll")                                               \
        for (int rr_ = (RB); rr_ < (RB) + 2; rr_++) {                   \
            int row_ = bn0 + rr_;                                       \
            int ig_ = i_base + row_;                                    \
            int p_ = ig_ & 1;                                           \
            uint32_t su_ = (uint32_t)((DD + k0_ - ig_ - p_) >> 1) * 4 + lane * 4; \
            uint32_t dst_ = bb_ + (uint32_t)row_ * ROWB + lane * 4;     \
            sts32(dst_, lds32(sAsp + p_ * 4096 + su_));                 \
            sts32(dst_ + 128, lds32(sAsp + (2 + p_) * 4096 + su_));     \
        }                                                               \
    } while (0)

    // ---- prologue: aspect copies + A(0) in one group ----
    {
        const char* pAsp = (const char*)(g_asp + b * 4 * 2048);
        cpasync16(sAsp + tid * 16, pAsp + tid * 16);
        cpasync16(sAsp + (tid + 512) * 16, pAsp + (size_t)(tid + 512) * 16);
    }
    LOAD_A(0, 0);

    asm volatile("cp.async.wait_group 0;" ::: "memory");
    __syncthreads();
    BUILD_B2(0, 0); BUILD_B2(0, 2); BUILD_B2(0, 4); BUILD_B2(0, 6);

    #pragma unroll 2
    for (int c = 0; c < NCHUNK; c++) {
        if (c > 0) {
            asm volatile("cp.async.wait_group 0;" ::: "memory");
            __syncthreads();
        }
        if (c + 1 < NCHUNK) LOAD_A((c + 1) & 1, c + 1);

        const uint32_t sa = sbase + (c & 1) * ASTG;
        const uint32_t sb = sB + (c & 1) * BSTG;
        const bool more = (c + 1 < NCHUNK);

        #pragma unroll
        for (int kk = 0; kk < 4; kk++) {
            // A layout per 256B: [kc0 hi64|kc0 lo64|kc1 hi64|kc1 lo64]
            const uint32_t akb = (uint32_t)((kk >> 1) * 128 + (kk & 1) * 32);
            // B layout per 256B: [hi 128 | lo 128]
            const uint32_t bkb = (uint32_t)(kk * 32);
            uint32_t aH[4][4], aL[4][4], bH[2][4], bL[2][4];
            #pragma unroll
            for (int mt = 0; mt < 4; mt++)
                ldsm4(aH[mt], sa + a_lane + mt * 16 * ROWB + akb);
            #pragma unroll
            for (int p = 0; p < 2; p++)
                ldsm4(bH[p], sb + b_lane + p * 16 * ROWB + bkb);
            #pragma unroll
            for (int p = 0; p < 2; p++)
                ldsm4(bL[p], sb + b_lane + p * 16 * ROWB + bkb + 128);
            #pragma unroll
            for (int mt = 0; mt < 4; mt++)
                #pragma unroll
                for (int nt = 0; nt < 4; nt++)
                    mma16816(acc[mt][nt], aH[mt], &bH[nt >> 1][2 * (nt & 1)]);
            // interleave B-build for next chunk (2 rows per kk step)
            if (more) BUILD_B2(c + 1, kk * 2);
            #pragma unroll
            for (int mt = 0; mt < 4; mt++)
                #pragma unroll
                for (int nt = 0; nt < 4; nt++)
                    mma16816(acc[mt][nt], aH[mt], &bL[nt >> 1][2 * (nt & 1)]);
            #pragma unroll
            for (int mt = 0; mt < 4; mt++)
                ldsm4(aL[mt], sa + a_lane + mt * 16 * ROWB + akb + 64);
            #pragma unroll
            for (int mt = 0; mt < 4; mt++)
                #pragma unroll
                for (int nt = 0; nt < 4; nt++)
                    mma16816(acc[mt][nt], aL[mt], &bH[nt >> 1][2 * (nt & 1)]);
        }
    }

    // ---- epilogue: direct f32 stores ----
    #pragma unroll
    for (int mt = 0; mt < 4; mt++) {
        int rr = s_base + wm * 64 + mt * 16 + (lane >> 2);
        float* p0 = out + ((size_t)b * SS + rr) * DD + i_base + wn * 32 + (lane & 3) * 2;
        float* p1 = p0 + (size_t)8 * DD;
        #pragma unroll
        for (int nt = 0; nt < 4; nt++) {
            *(float2*)(p0 + nt * 8) = make_float2(acc[mt][nt][0], acc[mt][nt][1]);
            *(float2*)(p1 + nt * 8) = make_float2(acc[mt][nt][2], acc[mt][nt][3]);
        }
    }
}

// ============================ launch ============================
extern "C" void kernel_launch(void* const* d_in, const int* in_sizes, int n_in,
                              void* d_out, int out_size) {
    const float* emb = (const float*)d_in[0];   // (32, 512, 1024) f32
    const float* asp = (const float*)d_in[1];   // (32, 1024) f32
    float* out = (float*)d_out;                 // (32, 512, 1024) f32

    cudaFuncSetAttribute(gemm_kernel, cudaFuncAttributeMaxDynamicSharedMemorySize, SMEM_DYN);

    anorm_kernel<<<BB, 256>>>(asp);
    esplit_kernel<<<dim3(SS, BB), 256>>>(emb);
    gemm_kernel<<<dim3(DD / 128, SS / 256, BB), 512, SMEM_DYN>>>(out);
}